// round 10
// baseline (speedup 1.0000x reference)
#include <cuda_runtime.h>
#include <cuda_bf16.h>
#include <cstdint>

#define BSZ 4
#define SEQ 1024
#define DMODEL 2048
#define NHEADS 32
#define NKV 8
#define HDIM 64
#define KVDIM 512
#define MROWS (BSZ*SEQ)
#define QKVN 3072          // packed Q|K|V columns

// ---------------------------------------------------------------------------
// Scratch (device globals)
// ---------------------------------------------------------------------------
__device__ __nv_bfloat16 g_xh[MROWS*DMODEL],  g_xl[MROWS*DMODEL];
__device__ __nv_bfloat16 g_qkvh[MROWS*QKVN],  g_qkvl[MROWS*QKVN];
__device__ __nv_bfloat16 g_ch[MROWS*DMODEL],  g_cl[MROWS*DMODEL];
__device__ __nv_bfloat16 g_wh[DMODEL*QKVN],   g_wl[DMODEL*QKVN];   // packed W [K,N]
__device__ __nv_bfloat16 g_woh[DMODEL*DMODEL], g_wol[DMODEL*DMODEL];
__device__ float g_bqkv[QKVN];

// ---------------------------------------------------------------------------
// PTX helpers
// ---------------------------------------------------------------------------
__device__ __forceinline__ uint32_t smem_u32(const void* p) {
    return (uint32_t)__cvta_generic_to_shared(p);
}
__device__ __forceinline__ void ldx4(uint32_t r[4], uint32_t addr) {
    asm volatile("ldmatrix.sync.aligned.m8n8.x4.shared.b16 {%0,%1,%2,%3}, [%4];"
                 : "=r"(r[0]), "=r"(r[1]), "=r"(r[2]), "=r"(r[3]) : "r"(addr));
}
__device__ __forceinline__ void ldx4t(uint32_t r[4], uint32_t addr) {
    asm volatile("ldmatrix.sync.aligned.m8n8.x4.trans.shared.b16 {%0,%1,%2,%3}, [%4];"
                 : "=r"(r[0]), "=r"(r[1]), "=r"(r[2]), "=r"(r[3]) : "r"(addr));
}
// NON-volatile: register-only op; lets nvcc/ptxas interleave independent MMAs.
__device__ __forceinline__ void mma16816(float c[4], const uint32_t a[4], const uint32_t b[2]) {
    asm("mma.sync.aligned.m16n8k16.row.col.f32.bf16.bf16.f32 "
        "{%0,%1,%2,%3}, {%4,%5,%6,%7}, {%8,%9}, {%0,%1,%2,%3};"
        : "+f"(c[0]), "+f"(c[1]), "+f"(c[2]), "+f"(c[3])
        : "r"(a[0]), "r"(a[1]), "r"(a[2]), "r"(a[3]), "r"(b[0]), "r"(b[1]));
}
__device__ __forceinline__ void cp16s(uint32_t dst, const void* src) {
    asm volatile("cp.async.cg.shared.global [%0], [%1], 16;" :: "r"(dst), "l"(src));
}
#define CP_COMMIT() asm volatile("cp.async.commit_group;")
#define CP_WAIT0()  asm volatile("cp.async.wait_group 0;")
#define CP_WAIT1()  asm volatile("cp.async.wait_group 1;")
#define CP_WAIT2()  asm volatile("cp.async.wait_group 2;")
__device__ __forceinline__ float ex2(float x) {
    float r; asm("ex2.approx.f32 %0, %1;" : "=f"(r) : "f"(x)); return r;
}

// ---------------------------------------------------------------------------
// fp32 -> (bf16 hi, bf16 lo) elementwise split (for x)
// ---------------------------------------------------------------------------
__global__ void split_kernel(const float4* __restrict__ in,
                             __nv_bfloat162* __restrict__ hi,
                             __nv_bfloat162* __restrict__ lo, int n4)
{
    int i = blockIdx.x * blockDim.x + threadIdx.x;
    if (i >= n4) return;
    float4 f = in[i];
    __nv_bfloat16 h0 = __float2bfloat16(f.x), h1 = __float2bfloat16(f.y);
    __nv_bfloat16 h2 = __float2bfloat16(f.z), h3 = __float2bfloat16(f.w);
    hi[2*i]   = __halves2bfloat162(h0, h1);
    hi[2*i+1] = __halves2bfloat162(h2, h3);
    lo[2*i]   = __floats2bfloat162_rn(f.x - __bfloat162float(h0), f.y - __bfloat162float(h1));
    lo[2*i+1] = __floats2bfloat162_rn(f.z - __bfloat162float(h2), f.w - __bfloat162float(h3));
}

// Split W[K,Nsrc] into packed hi/lo at column offset (ld = ldo)
__global__ void wsplit_kernel(const float* __restrict__ W,
                              __nv_bfloat16* __restrict__ oh,
                              __nv_bfloat16* __restrict__ ol,
                              int Nsrc, int coloff, int ldo, int n4)
{
    int i = blockIdx.x * blockDim.x + threadIdx.x;
    if (i >= n4) return;
    int k  = i / (Nsrc >> 2);
    int c4 = (i - k * (Nsrc >> 2)) << 2;
    float4 f = *(const float4*)&W[(size_t)k * Nsrc + c4];
    __nv_bfloat16 h0 = __float2bfloat16(f.x), h1 = __float2bfloat16(f.y);
    __nv_bfloat16 h2 = __float2bfloat16(f.z), h3 = __float2bfloat16(f.w);
    size_t o = (size_t)k * ldo + coloff + c4;
    *(__nv_bfloat162*)&oh[o]     = __halves2bfloat162(h0, h1);
    *(__nv_bfloat162*)&oh[o + 2] = __halves2bfloat162(h2, h3);
    *(__nv_bfloat162*)&ol[o]     =
        __floats2bfloat162_rn(f.x - __bfloat162float(h0), f.y - __bfloat162float(h1));
    *(__nv_bfloat162*)&ol[o + 2] =
        __floats2bfloat162_rn(f.z - __bfloat162float(h2), f.w - __bfloat162float(h3));
}

__global__ void bias_concat(const float* __restrict__ bq, const float* __restrict__ bk,
                            const float* __restrict__ bv, float* __restrict__ o)
{
    int i = blockIdx.x * 256 + threadIdx.x;
    if (i >= QKVN) return;
    o[i] = (i < DMODEL) ? bq[i] : (i < DMODEL + KVDIM) ? bk[i - DMODEL] : bv[i - DMODEL - KVDIM];
}

// ---------------------------------------------------------------------------
// Split-bf16 MMA GEMM: C[M,N] = A[M,K] @ W[K,N] + bias
// C = AhBh + AhBl + AlBh, TERM-MAJOR issue order (same-acc distance 16).
// Block 128x128, BK=32, 8 warps (warp 64x32), 3-stage cp.async pipeline.
// ---------------------------------------------------------------------------
#define APITCH 80    // bytes per A row (32 bf16 = 64B + 16B pad)
#define BPITCH 272   // bytes per B row (128 bf16 = 256B + 16B pad)
#define GA_H 0
#define GA_L 10240
#define GB_H 20480
#define GB_L 29184
#define GSTAGE 37888
#define GSTAGES 3
#define GEMM_SMEM (GSTAGES*GSTAGE)

__global__ __launch_bounds__(256) void mma_gemm(
    const __nv_bfloat16* __restrict__ Ahg, const __nv_bfloat16* __restrict__ Alg,
    const __nv_bfloat16* __restrict__ Bhg, const __nv_bfloat16* __restrict__ Blg,
    const float* __restrict__ bias,
    __nv_bfloat16* __restrict__ Ch, __nv_bfloat16* __restrict__ Cl,
    float* __restrict__ Cf,
    int N, int K)
{
    extern __shared__ __align__(16) char smem[];
    const uint32_t sb = smem_u32(smem);

    const int tid  = threadIdx.x;
    const int lane = tid & 31;
    const int warp = tid >> 5;
    const int wm = (warp & 1) * 64;
    const int wn = (warp >> 1) * 32;
    const int bm = blockIdx.y * 128;
    const int bn = blockIdx.x * 128;

    const int ar = tid >> 1, ach = (tid & 1) * 2;
    const int br = tid >> 4, bch = tid & 15;

    const int a_row = lane & 15;
    const int a_col = (lane >> 4) * 8;
    const int b_row = ((lane >> 3) & 1) * 8 + (lane & 7);
    const int b_col = (lane >> 4) * 8;

    float acc[4][4][4];
#pragma unroll
    for (int i = 0; i < 4; i++)
#pragma unroll
        for (int j = 0; j < 4; j++)
#pragma unroll
            for (int v = 0; v < 4; v++) acc[i][j][v] = 0.f;

    const int NITER = K >> 5;

    auto load_stage = [&](int s, int buf) {
        const uint32_t base = sb + buf * GSTAGE;
        const int k0 = s << 5;
#pragma unroll
        for (int j = 0; j < 2; j++) {
            int ch = ach + j;
            uint32_t off = (uint32_t)(ar * APITCH + ch * 16);
            cp16s(base + GA_H + off, Ahg + (size_t)(bm + ar) * K + k0 + ch * 8);
            cp16s(base + GA_L + off, Alg + (size_t)(bm + ar) * K + k0 + ch * 8);
        }
#pragma unroll
        for (int j = 0; j < 2; j++) {
            int r = br + j * 16;
            uint32_t off = (uint32_t)(r * BPITCH + bch * 16);
            cp16s(base + GB_H + off, Bhg + (size_t)(k0 + r) * N + bn + bch * 8);
            cp16s(base + GB_L + off, Blg + (size_t)(k0 + r) * N + bn + bch * 8);
        }
        CP_COMMIT();
    };

    load_stage(0, 0);
    load_stage(1, 1);

    int buf = 0;
#pragma unroll 1
    for (int s = 0; s < NITER; ++s) {
        if (s + 2 < NITER) {
            int nb = buf + 2; if (nb >= GSTAGES) nb -= GSTAGES;
            load_stage(s + 2, nb);
            CP_WAIT2();
        } else {
            CP_WAIT0();
        }
        __syncthreads();

        const uint32_t base = sb + buf * GSTAGE;
#pragma unroll
        for (int ks = 0; ks < 2; ks++) {
            uint32_t ah[4][4], al[4][4];
#pragma unroll
            for (int mt = 0; mt < 4; mt++) {
                uint32_t ao = base + GA_H + (wm + mt * 16 + a_row) * APITCH + (ks * 16 + a_col) * 2;
                ldx4(ah[mt], ao);
                ldx4(al[mt], ao + (GA_L - GA_H));
            }
            uint32_t bh[4][2], bl[4][2];
#pragma unroll
            for (int np = 0; np < 2; np++) {
                uint32_t bo = base + GB_H + (ks * 16 + b_row) * BPITCH + (wn + np * 16 + b_col) * 2;
                uint32_t r[4];
                ldx4t(r, bo);
                bh[np*2][0] = r[0]; bh[np*2][1] = r[1];
                bh[np*2+1][0] = r[2]; bh[np*2+1][1] = r[3];
                ldx4t(r, bo + (GB_L - GB_H));
                bl[np*2][0] = r[0]; bl[np*2][1] = r[1];
                bl[np*2+1][0] = r[2]; bl[np*2+1][1] = r[3];
            }
            // ---- term-major: pass over all 16 accumulators per term ----
#pragma unroll
            for (int mt = 0; mt < 4; mt++)
#pragma unroll
                for (int nt = 0; nt < 4; nt++)
                    mma16816(acc[mt][nt], ah[mt], bh[nt]);
#pragma unroll
            for (int mt = 0; mt < 4; mt++)
#pragma unroll
                for (int nt = 0; nt < 4; nt++)
                    mma16816(acc[mt][nt], ah[mt], bl[nt]);
#pragma unroll
            for (int mt = 0; mt < 4; mt++)
#pragma unroll
                for (int nt = 0; nt < 4; nt++)
                    mma16816(acc[mt][nt], al[mt], bh[nt]);
        }
        __syncthreads();
        if (++buf == GSTAGES) buf = 0;
    }

    // epilogue
    const int er = lane >> 2;
    const int ec = (lane & 3) * 2;
#pragma unroll
    for (int mt = 0; mt < 4; mt++) {
#pragma unroll
        for (int nt = 0; nt < 4; nt++) {
            int row = bm + wm + mt * 16 + er;
            int col = bn + wn + nt * 8 + ec;
            float b0 = bias[col], b1 = bias[col + 1];
            float v00 = acc[mt][nt][0] + b0, v01 = acc[mt][nt][1] + b1;
            float v10 = acc[mt][nt][2] + b0, v11 = acc[mt][nt][3] + b1;
            if (Cf) {
                *(float2*)&Cf[(size_t)row * N + col]       = make_float2(v00, v01);
                *(float2*)&Cf[(size_t)(row + 8) * N + col] = make_float2(v10, v11);
            } else {
                __nv_bfloat16 h00 = __float2bfloat16(v00), h01 = __float2bfloat16(v01);
                __nv_bfloat16 h10 = __float2bfloat16(v10), h11 = __float2bfloat16(v11);
                *(__nv_bfloat162*)&Ch[(size_t)row * N + col] = __halves2bfloat162(h00, h01);
                *(__nv_bfloat162*)&Cl[(size_t)row * N + col] =
                    __floats2bfloat162_rn(v00 - __bfloat162float(h00), v01 - __bfloat162float(h01));
                *(__nv_bfloat162*)&Ch[(size_t)(row + 8) * N + col] = __halves2bfloat162(h10, h11);
                *(__nv_bfloat162*)&Cl[(size_t)(row + 8) * N + col] =
                    __floats2bfloat162_rn(v10 - __bfloat162float(h10), v11 - __bfloat162float(h11));
            }
        }
    }
}

// ---------------------------------------------------------------------------
// Flash attention, GQA-grouped (CTA = KV group x 32 q-rows x 4 heads, M=128).
// Double-buffered K/V stages; term-major MMA issue in S and PV loops.
// Grid (SEQ/32, BSZ*NKV) = (32, 32). 256 threads, 8 warps x 16 M-rows.
// ---------------------------------------------------------------------------
#define FQP 72
#define F_KH 0
#define F_KL 18432
#define F_VH 36864
#define F_VL 55296
#define FSTAGE 73728
#define FLASH_SMEM (2*FSTAGE)

__global__ __launch_bounds__(256) void flash_mma_kernel()
{
    extern __shared__ __align__(16) char smem[];
    const uint32_t sb = smem_u32(smem);

    const int tid  = threadIdx.x;
    const int lane = tid & 31;
    const int warp = tid >> 5;

    const int gid = blockIdx.y;          // b * NKV + kvh
    const int b   = gid >> 3;
    const int kvh = gid & 7;
    const int q0  = blockIdx.x * 32;

    const __nv_bfloat16* QKVh = g_qkvh;
    const __nv_bfloat16* QKVl = g_qkvl;

    // ---- stage Q into buf0 K region, extract fragments ----
#pragma unroll
    for (int l = 0; l < 4; l++) {
        int id = tid + l * 256;
        int m = id >> 3, ch = id & 7;
        size_t src = (size_t)(b * SEQ + q0 + (m & 31)) * QKVN
                   + (kvh * 4 + (m >> 5)) * HDIM + ch * 8;
        uint32_t dst = sb + (uint32_t)(m * (FQP * 2) + ch * 16);
        cp16s(dst + F_KH, QKVh + src);
        cp16s(dst + F_KL, QKVl + src);
    }
    CP_COMMIT(); CP_WAIT0();
    __syncthreads();

    const int a_row = lane & 15;
    const int a_col = (lane >> 4) * 8;
    uint32_t qh[4][4], ql[4][4];
#pragma unroll
    for (int ks = 0; ks < 4; ks++) {
        uint32_t ao = sb + (warp * 16 + a_row) * (FQP * 2) + (ks * 16 + a_col) * 2;
        ldx4(qh[ks], ao + F_KH);
        ldx4(ql[ks], ao + F_KL);
    }
    __syncthreads();   // all warps done reading Q before buf0 reuse

    const size_t kbase = (size_t)(b * SEQ) * QKVN + DMODEL + kvh * HDIM;
    auto load_kv = [&](int kb, int buf) {
        const uint32_t base = sb + buf * FSTAGE;
#pragma unroll
        for (int l = 0; l < 4; l++) {
            int id = tid + l * 256;
            int r = id >> 3, ch = id & 7;
            size_t go = kbase + (size_t)(kb * 128 + r) * QKVN + ch * 8;
            uint32_t dst = base + (uint32_t)(r * (FQP * 2) + ch * 16);
            cp16s(dst + F_KH, QKVh + go);
            cp16s(dst + F_KL, QKVl + go);
            cp16s(dst + F_VH, QKVh + go + KVDIM);
            cp16s(dst + F_VL, QKVl + go + KVDIM);
        }
        CP_COMMIT();
    };

    load_kv(0, 0);
    load_kv(1, 1);

    float s[16][4];
    float o[8][4];
#pragma unroll
    for (int i = 0; i < 8; i++)
#pragma unroll
        for (int j = 0; j < 4; j++) o[i][j] = 0.f;
    float m0 = -1e30f, m1 = -1e30f, sum0 = 0.f, sum1 = 0.f;

    const int t_row = ((lane >> 3) & 1) * 8 + (lane & 7);
    const int t_col = (lane >> 4) * 8;

#pragma unroll 1
    for (int kb = 0; kb < SEQ / 128; kb++) {
        const int buf = kb & 1;
        const uint32_t base = sb + buf * FSTAGE;
        if (kb + 1 < SEQ / 128) CP_WAIT1(); else CP_WAIT0();
        __syncthreads();

        // ---- S = Q @ K^T (term-major over ntp pairs) ----
#pragma unroll
        for (int i = 0; i < 16; i++)
#pragma unroll
            for (int j = 0; j < 4; j++) s[i][j] = 0.f;

#pragma unroll
        for (int ks = 0; ks < 4; ks++) {
#pragma unroll
            for (int pp = 0; pp < 4; pp++) {
                const int p0 = 2 * pp, p1 = 2 * pp + 1;
                uint32_t ko0 = base + (p0 * 16 + a_row) * (FQP * 2) + (ks * 16 + a_col) * 2;
                uint32_t ko1 = base + (p1 * 16 + a_row) * (FQP * 2) + (ks * 16 + a_col) * 2;
                uint32_t rh0[4], rl0[4], rh1[4], rl1[4];
                ldx4(rh0, ko0 + F_KH);
                ldx4(rl0, ko0 + F_KL);
                ldx4(rh1, ko1 + F_KH);
                ldx4(rl1, ko1 + F_KL);
                uint32_t b0h0[2] = {rh0[0], rh0[2]}, b1h0[2] = {rh0[1], rh0[3]};
                uint32_t b0l0[2] = {rl0[0], rl0[2]}, b1l0[2] = {rl0[1], rl0[3]};
                uint32_t b0h1[2] = {rh1[0], rh1[2]}, b1h1[2] = {rh1[1], rh1[3]};
                uint32_t b0l1[2] = {rl1[0], rl1[2]}, b1l1[2] = {rl1[1], rl1[3]};
                // term hh (4 accs)
                mma16816(s[2*p0],   qh[ks], b0h0);
                mma16816(s[2*p0+1], qh[ks], b1h0);
                mma16816(s[2*p1],   qh[ks], b0h1);
                mma16816(s[2*p1+1], qh[ks], b1h1);
                // term hl
                mma16816(s[2*p0],   qh[ks], b0l0);
                mma16816(s[2*p0+1], qh[ks], b1l0);
                mma16816(s[2*p1],   qh[ks], b0l1);
                mma16816(s[2*p1+1], qh[ks], b1l1);
                // term lh
                mma16816(s[2*p0],   ql[ks], b0h0);
                mma16816(s[2*p0+1], ql[ks], b1h0);
                mma16816(s[2*p1],   ql[ks], b0h1);
                mma16816(s[2*p1+1], ql[ks], b1h1);
            }
        }

        // ---- online softmax (base-2 domain) ----
        const float C2 = 0.18033688011112042f;   // log2(e)/sqrt(64)
        float mx0 = -1e30f, mx1 = -1e30f;
#pragma unroll
        for (int i = 0; i < 16; i++) {
            s[i][0] *= C2; s[i][1] *= C2; s[i][2] *= C2; s[i][3] *= C2;
            mx0 = fmaxf(mx0, fmaxf(s[i][0], s[i][1]));
            mx1 = fmaxf(mx1, fmaxf(s[i][2], s[i][3]));
        }
        mx0 = fmaxf(mx0, __shfl_xor_sync(0xffffffffu, mx0, 1));
        mx0 = fmaxf(mx0, __shfl_xor_sync(0xffffffffu, mx0, 2));
        mx1 = fmaxf(mx1, __shfl_xor_sync(0xffffffffu, mx1, 1));
        mx1 = fmaxf(mx1, __shfl_xor_sync(0xffffffffu, mx1, 2));

        float nm0 = fmaxf(m0, mx0), nm1 = fmaxf(m1, mx1);
        float c0 = ex2(m0 - nm0), c1 = ex2(m1 - nm1);
        m0 = nm0; m1 = nm1;

        float rs0 = 0.f, rs1 = 0.f;
#pragma unroll
        for (int i = 0; i < 16; i++) {
            s[i][0] = ex2(s[i][0] - nm0); rs0 += s[i][0];
            s[i][1] = ex2(s[i][1] - nm0); rs0 += s[i][1];
            s[i][2] = ex2(s[i][2] - nm1); rs1 += s[i][2];
            s[i][3] = ex2(s[i][3] - nm1); rs1 += s[i][3];
        }
        rs0 += __shfl_xor_sync(0xffffffffu, rs0, 1);
        rs0 += __shfl_xor_sync(0xffffffffu, rs0, 2);
        rs1 += __shfl_xor_sync(0xffffffffu, rs1, 1);
        rs1 += __shfl_xor_sync(0xffffffffu, rs1, 2);
        sum0 = sum0 * c0 + rs0;
        sum1 = sum1 * c1 + rs1;
#pragma unroll
        for (int nt = 0; nt < 8; nt++) {
            o[nt][0] *= c0; o[nt][1] *= c0;
            o[nt][2] *= c1; o[nt][3] *= c1;
        }

        // ---- ctx += P @ V (term-major over np) ----
#pragma unroll
        for (int ks = 0; ks < 8; ks++) {
            float p00 = s[2*ks][0],   p01 = s[2*ks][1],   p10 = s[2*ks][2],   p11 = s[2*ks][3];
            float r00 = s[2*ks+1][0], r01 = s[2*ks+1][1], r10 = s[2*ks+1][2], r11 = s[2*ks+1][3];
            __nv_bfloat16 hp00 = __float2bfloat16(p00), hp01 = __float2bfloat16(p01);
            __nv_bfloat16 hp10 = __float2bfloat16(p10), hp11 = __float2bfloat16(p11);
            __nv_bfloat16 hr00 = __float2bfloat16(r00), hr01 = __float2bfloat16(r01);
            __nv_bfloat16 hr10 = __float2bfloat16(r10), hr11 = __float2bfloat16(r11);
            __nv_bfloat162 t;
            uint32_t ph[4], pl[4];
            t = __halves2bfloat162(hp00, hp01); ph[0] = *(uint32_t*)&t;
            t = __halves2bfloat162(hp10, hp11); ph[1] = *(uint32_t*)&t;
            t = __halves2bfloat162(hr00, hr01); ph[2] = *(uint32_t*)&t;
            t = __halves2bfloat162(hr10, hr11); ph[3] = *(uint32_t*)&t;
            t = __floats2bfloat162_rn(p00 - __bfloat162float(hp00), p01 - __bfloat162float(hp01)); pl[0] = *(uint32_t*)&t;
            t = __floats2bfloat162_rn(p10 - __bfloat162float(hp10), p11 - __bfloat162float(hp11)); pl[1] = *(uint32_t*)&t;
            t = __floats2bfloat162_rn(r00 - __bfloat162float(hr00), r01 - __bfloat162float(hr01)); pl[2] = *(uint32_t*)&t;
            t = __floats2bfloat162_rn(r10 - __bfloat162float(hr10), r11 - __bfloat162float(hr11)); pl[3] = *(uint32_t*)&t;

            uint32_t v0h[4][2], v1h[4][2], v0l[4][2], v1l[4][2];
#pragma unroll
            for (int np = 0; np < 4; np++) {
                uint32_t vo = base + (ks * 16 + t_row) * (FQP * 2) + (np * 16 + t_col) * 2;
                uint32_t vh4[4], vl4[4];
                ldx4t(vh4, vo + F_VH);
                ldx4t(vl4, vo + F_VL);
                v0h[np][0] = vh4[0]; v0h[np][1] = vh4[1];
                v1h[np][0] = vh4[2]; v1h[np][1] = vh4[3];
                v0l[np][0] = vl4[0]; v0l[np][1] = vl4[1];
                v1l[np][0] = vl4[2]; v1l[np][1] = vl4[3];
            }
            // term ph*vh (8 accs)
#pragma unroll
            for (int np = 0; np < 4; np++) {
                mma16816(o[np*2],   ph, v0h[np]);
                mma16816(o[np*2+1], ph, v1h[np]);
            }
            // term ph*vl
#pragma unroll
            for (int np = 0; np < 4; np++) {
                mma16816(o[np*2],   ph, v0l[np]);
                mma16816(o[np*2+1], ph, v1l[np]);
            }
            // term pl*vh
#pragma unroll
            for (int np = 0; np < 4; np++) {
                mma16816(o[np*2],   pl, v0h[np]);
                mma16816(o[np*2+1], pl, v1h[np]);
            }
        }

        __syncthreads();
        if (kb + 2 < SEQ / 128) load_kv(kb + 2, buf);
    }

    // ---- normalize + write ctx (hi/lo bf16) ----
    float inv0 = 1.f / sum0, inv1 = 1.f / sum1;
    const int head = kvh * 4 + (warp >> 1);
    const int row0 = b * SEQ + q0 + (warp & 1) * 16 + (lane >> 2);
    const int colb = head * HDIM + (lane & 3) * 2;
#pragma unroll
    for (int nt = 0; nt < 8; nt++) {
        int col = colb + nt * 8;
        float v00 = o[nt][0] * inv0, v01 = o[nt][1] * inv0;
        float v10 = o[nt][2] * inv1, v11 = o[nt][3] * inv1;
        __nv_bfloat16 h00 = __float2bfloat16(v00), h01 = __float2bfloat16(v01);
        __nv_bfloat16 h10 = __float2bfloat16(v10), h11 = __float2bfloat16(v11);
        size_t o0 = (size_t)row0 * DMODEL + col;
        size_t o1 = (size_t)(row0 + 8) * DMODEL + col;
        *(__nv_bfloat162*)&g_ch[o0] = __halves2bfloat162(h00, h01);
        *(__nv_bfloat162*)&g_cl[o0] =
            __floats2bfloat162_rn(v00 - __bfloat162float(h00), v01 - __bfloat162float(h01));
        *(__nv_bfloat162*)&g_ch[o1] = __halves2bfloat162(h10, h11);
        *(__nv_bfloat162*)&g_cl[o1] =
            __floats2bfloat162_rn(v10 - __bfloat162float(h10), v11 - __bfloat162float(h11));
    }
}

// ---------------------------------------------------------------------------
extern "C" void kernel_launch(void* const* d_in, const int* in_sizes, int n_in,
                              void* d_out, int out_size)
{
    const float* x  = (const float*)d_in[0];
    const float* Wq = (const float*)d_in[1];
    const float* bq = (const float*)d_in[2];
    const float* Wk = (const float*)d_in[3];
    const float* bk = (const float*)d_in[4];
    const float* Wv = (const float*)d_in[5];
    const float* bv = (const float*)d_in[6];
    const float* Wo = (const float*)d_in[7];
    const float* bo = (const float*)d_in[8];
    float* out = (float*)d_out;

    __nv_bfloat16 *xh, *xl, *qkvh, *qkvl, *ch, *cl, *wh, *wl, *woh, *wol;
    float* bqkv;
    cudaGetSymbolAddress((void**)&xh, g_xh);     cudaGetSymbolAddress((void**)&xl, g_xl);
    cudaGetSymbolAddress((void**)&qkvh, g_qkvh); cudaGetSymbolAddress((void**)&qkvl, g_qkvl);
    cudaGetSymbolAddress((void**)&ch, g_ch);     cudaGetSymbolAddress((void**)&cl, g_cl);
    cudaGetSymbolAddress((void**)&wh, g_wh);     cudaGetSymbolAddress((void**)&wl, g_wl);
    cudaGetSymbolAddress((void**)&woh, g_woh);   cudaGetSymbolAddress((void**)&wol, g_wol);
    cudaGetSymbolAddress((void**)&bqkv, g_bqkv);

    cudaFuncSetAttribute(mma_gemm, cudaFuncAttributeMaxDynamicSharedMemorySize, GEMM_SMEM);
    cudaFuncSetAttribute(flash_mma_kernel, cudaFuncAttributeMaxDynamicSharedMemorySize, FLASH_SMEM);

    // splits
    int nx = MROWS * DMODEL / 4;
    split_kernel<<<(nx + 255) / 256, 256>>>((const float4*)x,
                                            (__nv_bfloat162*)xh, (__nv_bfloat162*)xl, nx);
    int nq = DMODEL * DMODEL / 4, nk = DMODEL * KVDIM / 4;
    wsplit_kernel<<<(nq + 255) / 256, 256>>>(Wq, wh, wl, DMODEL, 0, QKVN, nq);
    wsplit_kernel<<<(nk + 255) / 256, 256>>>(Wk, wh, wl, KVDIM, DMODEL, QKVN, nk);
    wsplit_kernel<<<(nk + 255) / 256, 256>>>(Wv, wh, wl, KVDIM, DMODEL + KVDIM, QKVN, nk);
    wsplit_kernel<<<(nq + 255) / 256, 256>>>(Wo, woh, wol, DMODEL, 0, DMODEL, nq);
    bias_concat<<<(QKVN + 255) / 256, 256>>>(bq, bk, bv, bqkv);

    dim3 blk(256);
    // fused QKV projection
    mma_gemm<<<dim3(QKVN / 128, MROWS / 128), blk, GEMM_SMEM>>>(
        xh, xl, wh, wl, bqkv, qkvh, qkvl, nullptr, QKVN, DMODEL);

    // attention (GQA-grouped, double-buffered)
    flash_mma_kernel<<<dim3(SEQ / 32, BSZ * NKV), blk, FLASH_SMEM>>>();

    // output projection -> fp32 d_out
    mma_gemm<<<dim3(DMODEL / 128, MROWS / 128), blk, GEMM_SMEM>>>(
        ch, cl, woh, wol, bo, nullptr, nullptr, out, DMODEL, DMODEL);
}